// round 8
// baseline (speedup 1.0000x reference)
#include <cuda_runtime.h>
#include <cuda_bf16.h>
#include <cstdint>

#define BT_TOK 32768      // B*T = 16*2048
#define IN_DIM 768
#define ENC 512
#define CDIM 128
#define NCB 8
#define CBS 1024
#define KSPLIT 384        // 3 exact bf16 split planes [a|b|c] per row

// ---------------- scratch (static device globals; no allocations) ----------
__device__ float g_R[BT_TOK * ENC];                    // residual (64MB)
__device__ float g_Ze[BT_TOK * CDIM];                  // z_e fp32 (16MB)
__device__ __nv_bfloat16 g_zeS[(size_t)BT_TOK * KSPLIT]; // ze splits (25MB)
__device__ __nv_bfloat16 g_cbS[(size_t)NCB * CBS * KSPLIT]; // cb splits (6MB)
__device__ unsigned long long g_packed[BT_TOK];        // (distkey<<32)|idx
__device__ float g_cbnorm[NCB * CBS];                  // ||c||^2
__device__ float g_G[NCB * CBS * ENC];                 // cb @ out_w tables (16MB)
__device__ float g_lossPartial[NCB * BT_TOK];          // deterministic partials

// ---------------- helpers ----------------------------------------------------
__device__ __forceinline__ void cp16(uint32_t smem, const void* gmem) {
    asm volatile("cp.async.cg.shared.global [%0], [%1], 16;\n" :: "r"(smem), "l"(gmem));
}
__device__ __forceinline__ void cp16p(void* smem, const void* gmem) {
    cp16((uint32_t)__cvta_generic_to_shared(smem), gmem);
}
#define CP_COMMIT asm volatile("cp.async.commit_group;\n" ::)
#define CP_WAIT0  asm volatile("cp.async.wait_group 0;\n" ::)

__device__ __forceinline__ unsigned long long pack2(float lo, float hi) {
    unsigned long long r;
    asm("mov.b64 %0, {%1, %2};" : "=l"(r) : "f"(lo), "f"(hi));
    return r;
}
__device__ __forceinline__ void unpack2(float& lo, float& hi, unsigned long long v) {
    asm("mov.b64 {%0, %1}, %2;" : "=f"(lo), "=f"(hi) : "l"(v));
}
__device__ __forceinline__ void fma2(unsigned long long& d, unsigned long long a,
                                     unsigned long long b) {
    asm("fma.rn.f32x2 %0, %1, %2, %0;" : "+l"(d) : "l"(a), "l"(b));
}

#define LDMX4(r, addr) \
    asm volatile("ldmatrix.sync.aligned.m8n8.x4.shared.b16 {%0,%1,%2,%3}, [%4];" \
                 : "=r"((r)[0]), "=r"((r)[1]), "=r"((r)[2]), "=r"((r)[3]) : "r"(addr))
#define LDMX2(r, addr) \
    asm volatile("ldmatrix.sync.aligned.m8n8.x2.shared.b16 {%0,%1}, [%2];" \
                 : "=r"((r)[0]), "=r"((r)[1]) : "r"(addr))
#define MMA16816(c, a, b) \
    asm volatile("mma.sync.aligned.m16n8k16.row.col.f32.bf16.bf16.f32 " \
                 "{%0,%1,%2,%3}, {%4,%5,%6,%7}, {%8,%9}, {%0,%1,%2,%3};" \
                 : "+f"((c)[0]), "+f"((c)[1]), "+f"((c)[2]), "+f"((c)[3]) \
                 : "r"((a)[0]), "r"((a)[1]), "r"((a)[2]), "r"((a)[3]), \
                   "r"((b)[0]), "r"((b)[1]))

// plane-pair schedule: (aa, ab, ba, bb, ac, ca, bc, cb) — omits only c*c (~2^-32)
// SAME order as round 7 => bit-identical distance accumulation.
#define PA_TAB 0x21201100u
#define PB_TAB 0x12021010u

// ---------------- SGEMM: 128x128 tile, BK=16, smem DB, FFMA2 core ----------
// C = A @ B (+bias). SPLIT: also emit exact bf16x3 decomposition of C ([a|b|c]).
// Per-output fp32 accumulation chain: k strictly ascending (bit-identical R1-R7).
template<bool BIAS, bool SPLIT>
__global__ __launch_bounds__(256, 2) void sgemm4(
    const float* __restrict__ A, const float* __restrict__ B,
    float* __restrict__ C, const float* __restrict__ bias,
    __nv_bfloat16* __restrict__ splitOut, int K, int N,
    size_t strA, size_t strB, size_t strC)
{
    __shared__ float As[2][16][128];
    __shared__ float Bs[2][16][128];
    A += (size_t)blockIdx.z * strA;
    B += (size_t)blockIdx.z * strB;
    C += (size_t)blockIdx.z * strC;
    const int tid = threadIdx.x;
    const int tx = tid & 15, ty = tid >> 4;
    const int m0 = blockIdx.x * 128;
    const int n0 = blockIdx.y * 128;

    const int ar = tid & 127;
    const int ah = (tid >> 7) * 8;
    const int br = tid >> 4;
    const int bc = (tid & 15) * 4;

    const float* aptr = A + (size_t)(m0 + ar) * K;
    const float* bptr = B + n0;

    const int T = K >> 4;

    float4 av0 = *(const float4*)(aptr + ah);
    float4 av1 = *(const float4*)(aptr + ah + 4);
    cp16p(&Bs[0][br][bc],      bptr + (size_t)br * N + bc);
    cp16p(&Bs[0][br][bc + 64], bptr + (size_t)br * N + bc + 64);
    As[0][ah + 0][ar] = av0.x; As[0][ah + 1][ar] = av0.y;
    As[0][ah + 2][ar] = av0.z; As[0][ah + 3][ar] = av0.w;
    As[0][ah + 4][ar] = av1.x; As[0][ah + 5][ar] = av1.y;
    As[0][ah + 6][ar] = av1.z; As[0][ah + 7][ar] = av1.w;
    CP_COMMIT;
    CP_WAIT0;
    __syncthreads();

    unsigned long long acc2[8][4];
#pragma unroll
    for (int i = 0; i < 8; ++i)
#pragma unroll
        for (int j = 0; j < 4; ++j) acc2[i][j] = 0ull;

    for (int t = 0; t < T; ++t) {
        const int buf = t & 1;
        const bool pf = (t + 1 < T);
        const int kn = (t + 1) << 4;
        if (pf) {
            av0 = *(const float4*)(aptr + kn + ah);
            av1 = *(const float4*)(aptr + kn + ah + 4);
            cp16p(&Bs[buf ^ 1][br][bc],      bptr + (size_t)(kn + br) * N + bc);
            cp16p(&Bs[buf ^ 1][br][bc + 64], bptr + (size_t)(kn + br) * N + bc + 64);
            CP_COMMIT;
        }
#pragma unroll
        for (int k = 0; k < 16; ++k) {
            float a[8];
            *(float4*)(a)     = *(const float4*)&As[buf][k][ty * 8];
            *(float4*)(a + 4) = *(const float4*)&As[buf][k][ty * 8 + 4];
            float4 b0 = *(const float4*)&Bs[buf][k][tx * 8];
            float4 b1 = *(const float4*)&Bs[buf][k][tx * 8 + 4];
            unsigned long long bb[4];
            bb[0] = pack2(b0.x, b0.y); bb[1] = pack2(b0.z, b0.w);
            bb[2] = pack2(b1.x, b1.y); bb[3] = pack2(b1.z, b1.w);
#pragma unroll
            for (int i = 0; i < 8; ++i) {
                unsigned long long ai = pack2(a[i], a[i]);
#pragma unroll
                for (int j = 0; j < 4; ++j) fma2(acc2[i][j], ai, bb[j]);
            }
        }
        if (pf) {
            As[buf ^ 1][ah + 0][ar] = av0.x; As[buf ^ 1][ah + 1][ar] = av0.y;
            As[buf ^ 1][ah + 2][ar] = av0.z; As[buf ^ 1][ah + 3][ar] = av0.w;
            As[buf ^ 1][ah + 4][ar] = av1.x; As[buf ^ 1][ah + 5][ar] = av1.y;
            As[buf ^ 1][ah + 6][ar] = av1.z; As[buf ^ 1][ah + 7][ar] = av1.w;
            CP_WAIT0;
            __syncthreads();
        }
    }

#pragma unroll
    for (int i = 0; i < 8; ++i) {
        float c[8];
#pragma unroll
        for (int j = 0; j < 4; ++j) unpack2(c[2 * j], c[2 * j + 1], acc2[i][j]);
        int m = m0 + ty * 8 + i;
        float* crow = C + (size_t)m * N + n0 + tx * 8;
        if (BIAS) {
#pragma unroll
            for (int j = 0; j < 8; ++j) crow[j] = c[j] + bias[n0 + tx * 8 + j];
        } else {
#pragma unroll
            for (int j = 0; j < 8; ++j) crow[j] = c[j];
        }
        if (SPLIT) {
            __align__(16) __nv_bfloat16 pa[8], pb[8], pc[8];
#pragma unroll
            for (int j = 0; j < 8; ++j) {
                float x = c[j];
                __nv_bfloat16 va = __float2bfloat16(x);
                float r1 = x - __bfloat162float(va);
                __nv_bfloat16 vb = __float2bfloat16(r1);
                float r2 = r1 - __bfloat162float(vb);
                __nv_bfloat16 vc = __float2bfloat16(r2);
                pa[j] = va; pb[j] = vb; pc[j] = vc;
            }
            size_t off = (size_t)m * KSPLIT + n0 + tx * 8;
            *(uint4*)(splitOut + off)       = *(const uint4*)pa;
            *(uint4*)(splitOut + off + 128) = *(const uint4*)pb;
            *(uint4*)(splitOut + off + 256) = *(const uint4*)pc;
        }
    }
}

// ---------------- codebook split + norms -----------------------------------
__global__ void split_cb_kernel(const float* __restrict__ cb,
                                __nv_bfloat16* __restrict__ out)
{
    size_t i = (size_t)blockIdx.x * blockDim.x + threadIdx.x;
    if (i >= (size_t)NCB * CBS * CDIM) return;
    size_t row = i >> 7;
    int col = (int)(i & 127);
    float x = cb[i];
    __nv_bfloat16 va = __float2bfloat16(x);
    float r1 = x - __bfloat162float(va);
    __nv_bfloat16 vb = __float2bfloat16(r1);
    float r2 = r1 - __bfloat162float(vb);
    __nv_bfloat16* o = out + row * KSPLIT + col;
    o[0]   = va;
    o[128] = vb;
    o[256] = __float2bfloat16(r2);
}

__global__ void norm_kernel(const float* __restrict__ cb, float* __restrict__ out, int rows)
{
    int w = (blockIdx.x * blockDim.x + threadIdx.x) >> 5;
    int lane = threadIdx.x & 31;
    if (w >= rows) return;
    const float* r = cb + (size_t)w * CDIM;
    float s = 0.f;
#pragma unroll
    for (int q = 0; q < 4; ++q) { float v = r[lane + q * 32]; s += v * v; }
#pragma unroll
    for (int off = 16; off >= 1; off >>= 1) s += __shfl_xor_sync(0xffffffffu, s, off);
    if (lane == 0) out[w] = s;
}

// ---------------- mma.sync distance + argmin (chunked B, few syncs) ---------
// Per CTA: 128 tokens x 1024 codes. A = ze splits [a|b|c] resident (98KB);
// B = full 3-plane tile per 128-code chunk, loaded ONCE (98KB, single buffer).
// MMA accumulation order identical to round 7 (PA/PB tables, kc=0..15, ks
// ascending) => distances bit-identical => codes bit-identical.
#define ASTR 784                    // A smem row stride bytes (392 bf16)
#define BSTR 784                    // B smem row stride bytes (392 bf16)
#define DSM_A 0
#define DSM_B (128 * ASTR)          // 100352
#define DSM_BEST (DSM_B + 128 * BSTR) // 200704
#define DSM_TOT (DSM_BEST + 128 * 8)  // 201728

__global__ __launch_bounds__(256, 1) void distMMA_kernel(
    const __nv_bfloat16* __restrict__ zeS,   // [BT_TOK][384]
    const __nv_bfloat16* __restrict__ cbS,   // stage base [CBS][384]
    const float* __restrict__ cbn,           // stage base [CBS]
    unsigned long long* __restrict__ packed)
{
    extern __shared__ char smem[];
    const uint32_t sb = (uint32_t)__cvta_generic_to_shared(smem);
    unsigned long long* sbest = (unsigned long long*)(smem + DSM_BEST);
    const int tid = threadIdx.x;
    const int lane = tid & 31, wid = tid >> 5;
    const int rowband = wid & 3;            // 4 row bands of 32
    const int colhalf = wid >> 2;           // 2 col halves of 64
    const int gid = lane >> 2, tig = lane & 3;
    const int m0 = blockIdx.x * 128;

    if (tid < 128) sbest[tid] = ~0ull;

    // ---- load A (128 x 384 = [a|b|c]) once ----
    {
        const __nv_bfloat16* src = zeS + (size_t)m0 * KSPLIT;
#pragma unroll
        for (int it = 0; it < 24; ++it) {
            int idx = tid + it * 256;        // 0..6143
            int row = idx / 48, piece = idx % 48;
            cp16(sb + DSM_A + row * ASTR + piece * 16,
                 src + (size_t)row * KSPLIT + piece * 8);
        }
    }
    CP_COMMIT;

    // lane-fixed smem addresses
    const uint32_t aBase = sb + DSM_A + (rowband * 32 + (lane & 15)) * ASTR +
                           (lane >> 4) * 16;
    const uint32_t bBase = sb + DSM_B + (colhalf * 64 + (lane & 7)) * BSTR +
                           ((lane >> 3) & 1) * 16;

    float c[2][8][4];
#pragma unroll
    for (int rt = 0; rt < 2; ++rt)
#pragma unroll
        for (int ct = 0; ct < 8; ++ct)
#pragma unroll
            for (int v = 0; v < 4; ++v) c[rt][ct][v] = 0.f;

    for (int nc = 0; nc < 8; ++nc) {
        // ---- load full 3-plane B tile for this 128-code chunk ----
        {
            const __nv_bfloat16* src = cbS + (size_t)nc * 128 * KSPLIT;
#pragma unroll
            for (int it = 0; it < 24; ++it) {
                int idx = tid + it * 256;    // 0..6143
                int row = idx / 48, piece = idx % 48;
                cp16(sb + DSM_B + row * BSTR + piece * 16,
                     src + (size_t)row * KSPLIT + piece * 8);
            }
        }
        CP_COMMIT;
        CP_WAIT0;
        __syncthreads();

#pragma unroll
        for (int kc = 0; kc < 16; ++kc) {
            const uint32_t aplane = (PA_TAB >> ((kc >> 1) * 4)) & 15;
            const uint32_t bplane = (PB_TAB >> ((kc >> 1) * 4)) & 15;
            const uint32_t abyte = aplane * 256 + (kc & 1) * 128;
            const uint32_t bbyte = bplane * 256 + (kc & 1) * 128;
#pragma unroll
            for (int ks = 0; ks < 4; ++ks) {
                uint32_t a[2][4];
                const uint32_t aoff = abyte + ks * 32;
                LDMX4(a[0], aBase + aoff);
                LDMX4(a[1], aBase + 16 * ASTR + aoff);
                uint32_t b[8][2];
#pragma unroll
                for (int ct = 0; ct < 8; ++ct)
                    LDMX2(b[ct], bBase + ct * 8 * BSTR + bbyte + ks * 32);
#pragma unroll
                for (int rt = 0; rt < 2; ++rt)
#pragma unroll
                    for (int ct = 0; ct < 8; ++ct)
                        MMA16816(c[rt][ct], a[rt], b[ct]);
            }
        }

        // ---- epilogue for this code chunk (identical math/order to R7) ----
        {
            const int ncbase = nc * 128 + colhalf * 64;
#pragma unroll
            for (int rt = 0; rt < 2; ++rt) {
                unsigned long long bl0 = ~0ull, bl1 = ~0ull;
#pragma unroll
                for (int ct = 0; ct < 8; ++ct) {
                    const int n = ncbase + ct * 8 + tig * 2;
                    const float cn0 = cbn[n], cn1 = cbn[n + 1];
                    float d0 = cn0 - 2.0f * c[rt][ct][0];
                    float d1 = cn1 - 2.0f * c[rt][ct][1];
                    float d2 = cn0 - 2.0f * c[rt][ct][2];
                    float d3 = cn1 - 2.0f * c[rt][ct][3];
                    c[rt][ct][0] = 0.f; c[rt][ct][1] = 0.f;
                    c[rt][ct][2] = 0.f; c[rt][ct][3] = 0.f;
                    unsigned i0 = __float_as_uint(d0);
                    unsigned i1 = __float_as_uint(d1);
                    unsigned i2 = __float_as_uint(d2);
                    unsigned i3 = __float_as_uint(d3);
                    i0 ^= (i0 & 0x80000000u) ? 0xffffffffu : 0x80000000u;
                    i1 ^= (i1 & 0x80000000u) ? 0xffffffffu : 0x80000000u;
                    i2 ^= (i2 & 0x80000000u) ? 0xffffffffu : 0x80000000u;
                    i3 ^= (i3 & 0x80000000u) ? 0xffffffffu : 0x80000000u;
                    unsigned long long k0 = ((unsigned long long)i0 << 32) | (unsigned)n;
                    unsigned long long k1 = ((unsigned long long)i1 << 32) | (unsigned)(n + 1);
                    unsigned long long k2 = ((unsigned long long)i2 << 32) | (unsigned)n;
                    unsigned long long k3 = ((unsigned long long)i3 << 32) | (unsigned)(n + 1);
                    if (k1 < k0) k0 = k1;
                    if (k0 < bl0) bl0 = k0;
                    if (k3 < k2) k2 = k3;
                    if (k2 < bl1) bl1 = k2;
                }
#pragma unroll
                for (int off = 1; off <= 2; off <<= 1) {
                    unsigned long long o0 = __shfl_xor_sync(0xffffffffu, bl0, off);
                    unsigned long long o1 = __shfl_xor_sync(0xffffffffu, bl1, off);
                    if (o0 < bl0) bl0 = o0;
                    if (o1 < bl1) bl1 = o1;
                }
                if (tig == 0) {
                    const int rbase = rowband * 32 + rt * 16 + gid;
                    atomicMin(&sbest[rbase], bl0);
                    atomicMin(&sbest[rbase + 8], bl1);
                }
            }
        }
        __syncthreads();   // all warps done with B before next chunk overwrite
    }

    if (tid < 128) packed[m0 + tid] = sbest[tid];
}

// ---------------- per-token fused epilogue ----------------------------------
__global__ __launch_bounds__(128) void fused_update_kernel(
    const float* __restrict__ Ze, const float* __restrict__ cb,
    const float* __restrict__ G, const unsigned long long* __restrict__ packed,
    float* __restrict__ out_codes, int stage, float* __restrict__ partial,
    float* __restrict__ R)
{
    __shared__ float red[128];
    const int t = blockIdx.x;
    const int tid = threadIdx.x;
    const unsigned idx = (unsigned)(packed[t] & 0xffffffffu);

    float d = Ze[(size_t)t * CDIM + tid] - cb[(size_t)idx * CDIM + tid];
    red[tid] = d * d;
    __syncthreads();
#pragma unroll
    for (int st = 64; st > 0; st >>= 1) {
        if (tid < st) red[tid] += red[tid + st];
        __syncthreads();
    }
    if (tid == 0) {
        partial[t] = red[0];
        out_codes[(size_t)t * NCB + stage] = (float)idx;
    }

    float4* R4 = (float4*)(R + (size_t)t * ENC);
    const float4* G4 = (const float4*)(G + (size_t)idx * ENC);
    float4 r = R4[tid];
    float4 g = G4[tid];
    r.x -= g.x; r.y -= g.y; r.z -= g.z; r.w -= g.w;
    R4[tid] = r;
}

__global__ void final_loss_kernel(const float* __restrict__ partial, float* __restrict__ out)
{
    __shared__ float s[256];
    float v = 0.f;
    const int per = (NCB * BT_TOK) / 256;   // 1024
    for (int q = 0; q < per; ++q) v += partial[threadIdx.x * per + q];
    s[threadIdx.x] = v;
    __syncthreads();
    for (int st = 128; st > 0; st >>= 1) {
        if (threadIdx.x < st) s[threadIdx.x] += s[threadIdx.x + st];
        __syncthreads();
    }
    if (threadIdx.x == 0)
        out[(size_t)BT_TOK * NCB] = 1.25f * s[0] / (float)((size_t)BT_TOK * CDIM);
}

// ---------------- launch ----------------------------------------------------
extern "C" void kernel_launch(void* const* d_in, const int* in_sizes, int n_in,
                              void* d_out, int out_size)
{
    const float* z    = (const float*)d_in[0];   // (16,2048,768)
    const float* Win  = (const float*)d_in[1];   // (768,512)
    const float* bin  = (const float*)d_in[2];   // (512,)
    const float* cbs  = (const float*)d_in[3];   // (8,1024,128)
    const float* inw  = (const float*)d_in[4];   // (8,512,128)
    const float* outw = (const float*)d_in[5];   // (8,128,512)
    float* out = (float*)d_out;

    float *gR, *gZe, *gCbn, *gLP, *gG;
    __nv_bfloat16 *gZeS, *gCbS;
    unsigned long long* gPk;
    cudaGetSymbolAddress((void**)&gR,   g_R);
    cudaGetSymbolAddress((void**)&gZe,  g_Ze);
    cudaGetSymbolAddress((void**)&gZeS, g_zeS);
    cudaGetSymbolAddress((void**)&gCbS, g_cbS);
    cudaGetSymbolAddress((void**)&gCbn, g_cbnorm);
    cudaGetSymbolAddress((void**)&gLP,  g_lossPartial);
    cudaGetSymbolAddress((void**)&gG,   g_G);
    cudaGetSymbolAddress((void**)&gPk,  g_packed);

    cudaFuncSetAttribute(distMMA_kernel,
                         cudaFuncAttributeMaxDynamicSharedMemorySize, DSM_TOT);

    // 1. residual = z @ W_in + b_in
    sgemm4<true, false><<<dim3(BT_TOK / 128, ENC / 128, 1), 256>>>(
        z, Win, gR, bin, nullptr, IN_DIM, ENC, 0, 0, 0);

    // 2. codebook norms + exact bf16x3 splits ([a|b|c] layout)
    norm_kernel<<<(NCB * CBS * 32) / 256, 256>>>(cbs, gCbn, NCB * CBS);
    split_cb_kernel<<<(NCB * CBS * CDIM) / 256, 256>>>(cbs, gCbS);

    // 3. dec tables: G_i = cb_i @ out_w_i (batched over blockIdx.z)
    sgemm4<false, false><<<dim3(CBS / 128, ENC / 128, NCB), 256>>>(
        cbs, outw, gG, nullptr, nullptr, CDIM, ENC,
        (size_t)CBS * CDIM, (size_t)CDIM * ENC, (size_t)CBS * ENC);

    for (int i = 0; i < NCB; ++i) {
        const float* cb_i = cbs + (size_t)i * CBS * CDIM;

        // z_e = R @ in_w[i]  (fp32 + exact bf16x3 splits)
        sgemm4<false, true><<<dim3(BT_TOK / 128, CDIM / 128, 1), 256>>>(
            gR, inw + (size_t)i * ENC * CDIM, gZe, nullptr, gZeS, ENC, CDIM, 0, 0, 0);

        // distances + argmin on tensor cores (8 plane-pair passes, bit-identical)
        distMMA_kernel<<<BT_TOK / 128, 256, DSM_TOT>>>(
            gZeS, gCbS + (size_t)i * CBS * KSPLIT, gCbn + (size_t)i * CBS, gPk);

        // codes + loss partials + R -= G[idx]
        fused_update_kernel<<<BT_TOK, 128>>>(
            gZe, cb_i, gG + (size_t)i * CBS * ENC, gPk, out, i,
            gLP + (size_t)i * BT_TOK, gR);
    }

    final_loss_kernel<<<1, 256>>>(gLP, out);
}

// round 9
// speedup vs baseline: 1.1270x; 1.1270x over previous
#include <cuda_runtime.h>
#include <cuda_bf16.h>
#include <cstdint>

#define BT_TOK 32768      // B*T = 16*2048
#define IN_DIM 768
#define ENC 512
#define CDIM 128
#define NCB 8
#define CBS 1024
#define KSPLIT 384        // 3 exact bf16 split planes [a|b|c] per row

// ---------------- scratch (static device globals; no allocations) ----------
__device__ float g_R[BT_TOK * ENC];                    // residual (64MB)
__device__ float g_Ze[BT_TOK * CDIM];                  // z_e fp32 (16MB)
__device__ __nv_bfloat16 g_zeS[(size_t)BT_TOK * KSPLIT]; // ze splits (25MB)
__device__ __nv_bfloat16 g_cbS[(size_t)NCB * CBS * KSPLIT]; // cb splits (6MB)
__device__ unsigned long long g_packed[BT_TOK];        // (distkey<<32)|idx
__device__ float g_cbnorm[NCB * CBS];                  // ||c||^2
__device__ float g_G[NCB * CBS * ENC];                 // cb @ out_w tables (16MB)
__device__ float g_lossPartial[NCB * BT_TOK];          // deterministic partials

// ---------------- helpers ----------------------------------------------------
__device__ __forceinline__ void cp16(uint32_t smem, const void* gmem) {
    asm volatile("cp.async.cg.shared.global [%0], [%1], 16;\n" :: "r"(smem), "l"(gmem));
}
__device__ __forceinline__ void cp16p(void* smem, const void* gmem) {
    cp16((uint32_t)__cvta_generic_to_shared(smem), gmem);
}
#define CP_COMMIT asm volatile("cp.async.commit_group;\n" ::)
#define CP_WAIT0  asm volatile("cp.async.wait_group 0;\n" ::)
#define CP_WAIT1  asm volatile("cp.async.wait_group 1;\n" ::)

__device__ __forceinline__ unsigned long long pack2(float lo, float hi) {
    unsigned long long r;
    asm("mov.b64 %0, {%1, %2};" : "=l"(r) : "f"(lo), "f"(hi));
    return r;
}
__device__ __forceinline__ void unpack2(float& lo, float& hi, unsigned long long v) {
    asm("mov.b64 {%0, %1}, %2;" : "=f"(lo), "=f"(hi) : "l"(v));
}
__device__ __forceinline__ void fma2(unsigned long long& d, unsigned long long a,
                                     unsigned long long b) {
    asm("fma.rn.f32x2 %0, %1, %2, %0;" : "+l"(d) : "l"(a), "l"(b));
}

#define LDMX4(r, addr) \
    asm volatile("ldmatrix.sync.aligned.m8n8.x4.shared.b16 {%0,%1,%2,%3}, [%4];" \
                 : "=r"((r)[0]), "=r"((r)[1]), "=r"((r)[2]), "=r"((r)[3]) : "r"(addr))
#define LDMX2(r, addr) \
    asm volatile("ldmatrix.sync.aligned.m8n8.x2.shared.b16 {%0,%1}, [%2];" \
                 : "=r"((r)[0]), "=r"((r)[1]) : "r"(addr))
#define MMA16816(c, a, b) \
    asm volatile("mma.sync.aligned.m16n8k16.row.col.f32.bf16.bf16.f32 " \
                 "{%0,%1,%2,%3}, {%4,%5,%6,%7}, {%8,%9}, {%0,%1,%2,%3};" \
                 : "+f"((c)[0]), "+f"((c)[1]), "+f"((c)[2]), "+f"((c)[3]) \
                 : "r"((a)[0]), "r"((a)[1]), "r"((a)[2]), "r"((a)[3]), \
                   "r"((b)[0]), "r"((b)[1]))

// plane-pair schedule: (aa, ab, ba, bb, ac, ca, bc, cb) — omits only c*c (~2^-32)
// SAME order as rounds 7/8 => bit-identical distance accumulation.
#define PA_TAB 0x21201100u
#define PB_TAB 0x12021010u

// ---------------- SGEMM: 128x128 tile, BK=16, smem DB, FFMA2 core ----------
// C = A @ B (+bias). SPLIT: also emit exact bf16x3 decomposition of C ([a|b|c]).
// Per-output fp32 accumulation chain: k strictly ascending (bit-identical R1-R8).
template<bool BIAS, bool SPLIT>
__global__ __launch_bounds__(256, 2) void sgemm4(
    const float* __restrict__ A, const float* __restrict__ B,
    float* __restrict__ C, const float* __restrict__ bias,
    __nv_bfloat16* __restrict__ splitOut, int K, int N,
    size_t strA, size_t strB, size_t strC)
{
    __shared__ float As[2][16][128];
    __shared__ float Bs[2][16][128];
    A += (size_t)blockIdx.z * strA;
    B += (size_t)blockIdx.z * strB;
    C += (size_t)blockIdx.z * strC;
    const int tid = threadIdx.x;
    const int tx = tid & 15, ty = tid >> 4;
    const int m0 = blockIdx.x * 128;
    const int n0 = blockIdx.y * 128;

    const int ar = tid & 127;
    const int ah = (tid >> 7) * 8;
    const int br = tid >> 4;
    const int bc = (tid & 15) * 4;

    const float* aptr = A + (size_t)(m0 + ar) * K;
    const float* bptr = B + n0;

    const int T = K >> 4;

    float4 av0 = *(const float4*)(aptr + ah);
    float4 av1 = *(const float4*)(aptr + ah + 4);
    cp16p(&Bs[0][br][bc],      bptr + (size_t)br * N + bc);
    cp16p(&Bs[0][br][bc + 64], bptr + (size_t)br * N + bc + 64);
    As[0][ah + 0][ar] = av0.x; As[0][ah + 1][ar] = av0.y;
    As[0][ah + 2][ar] = av0.z; As[0][ah + 3][ar] = av0.w;
    As[0][ah + 4][ar] = av1.x; As[0][ah + 5][ar] = av1.y;
    As[0][ah + 6][ar] = av1.z; As[0][ah + 7][ar] = av1.w;
    CP_COMMIT;
    CP_WAIT0;
    __syncthreads();

    unsigned long long acc2[8][4];
#pragma unroll
    for (int i = 0; i < 8; ++i)
#pragma unroll
        for (int j = 0; j < 4; ++j) acc2[i][j] = 0ull;

    for (int t = 0; t < T; ++t) {
        const int buf = t & 1;
        const bool pf = (t + 1 < T);
        const int kn = (t + 1) << 4;
        if (pf) {
            av0 = *(const float4*)(aptr + kn + ah);
            av1 = *(const float4*)(aptr + kn + ah + 4);
            cp16p(&Bs[buf ^ 1][br][bc],      bptr + (size_t)(kn + br) * N + bc);
            cp16p(&Bs[buf ^ 1][br][bc + 64], bptr + (size_t)(kn + br) * N + bc + 64);
            CP_COMMIT;
        }
#pragma unroll
        for (int k = 0; k < 16; ++k) {
            float a[8];
            *(float4*)(a)     = *(const float4*)&As[buf][k][ty * 8];
            *(float4*)(a + 4) = *(const float4*)&As[buf][k][ty * 8 + 4];
            float4 b0 = *(const float4*)&Bs[buf][k][tx * 8];
            float4 b1 = *(const float4*)&Bs[buf][k][tx * 8 + 4];
            unsigned long long bb[4];
            bb[0] = pack2(b0.x, b0.y); bb[1] = pack2(b0.z, b0.w);
            bb[2] = pack2(b1.x, b1.y); bb[3] = pack2(b1.z, b1.w);
#pragma unroll
            for (int i = 0; i < 8; ++i) {
                unsigned long long ai = pack2(a[i], a[i]);
#pragma unroll
                for (int j = 0; j < 4; ++j) fma2(acc2[i][j], ai, bb[j]);
            }
        }
        if (pf) {
            As[buf ^ 1][ah + 0][ar] = av0.x; As[buf ^ 1][ah + 1][ar] = av0.y;
            As[buf ^ 1][ah + 2][ar] = av0.z; As[buf ^ 1][ah + 3][ar] = av0.w;
            As[buf ^ 1][ah + 4][ar] = av1.x; As[buf ^ 1][ah + 5][ar] = av1.y;
            As[buf ^ 1][ah + 6][ar] = av1.z; As[buf ^ 1][ah + 7][ar] = av1.w;
            CP_WAIT0;
            __syncthreads();
        }
    }

#pragma unroll
    for (int i = 0; i < 8; ++i) {
        float c[8];
#pragma unroll
        for (int j = 0; j < 4; ++j) unpack2(c[2 * j], c[2 * j + 1], acc2[i][j]);
        int m = m0 + ty * 8 + i;
        float* crow = C + (size_t)m * N + n0 + tx * 8;
        if (BIAS) {
#pragma unroll
            for (int j = 0; j < 8; ++j) crow[j] = c[j] + bias[n0 + tx * 8 + j];
        } else {
#pragma unroll
            for (int j = 0; j < 8; ++j) crow[j] = c[j];
        }
        if (SPLIT) {
            __align__(16) __nv_bfloat16 pa[8], pb[8], pc[8];
#pragma unroll
            for (int j = 0; j < 8; ++j) {
                float x = c[j];
                __nv_bfloat16 va = __float2bfloat16(x);
                float r1 = x - __bfloat162float(va);
                __nv_bfloat16 vb = __float2bfloat16(r1);
                float r2 = r1 - __bfloat162float(vb);
                __nv_bfloat16 vc = __float2bfloat16(r2);
                pa[j] = va; pb[j] = vb; pc[j] = vc;
            }
            size_t off = (size_t)m * KSPLIT + n0 + tx * 8;
            *(uint4*)(splitOut + off)       = *(const uint4*)pa;
            *(uint4*)(splitOut + off + 128) = *(const uint4*)pb;
            *(uint4*)(splitOut + off + 256) = *(const uint4*)pc;
        }
    }
}

// ---------------- codebook split + norms -----------------------------------
__global__ void split_cb_kernel(const float* __restrict__ cb,
                                __nv_bfloat16* __restrict__ out)
{
    size_t i = (size_t)blockIdx.x * blockDim.x + threadIdx.x;
    if (i >= (size_t)NCB * CBS * CDIM) return;
    size_t row = i >> 7;
    int col = (int)(i & 127);
    float x = cb[i];
    __nv_bfloat16 va = __float2bfloat16(x);
    float r1 = x - __bfloat162float(va);
    __nv_bfloat16 vb = __float2bfloat16(r1);
    float r2 = r1 - __bfloat162float(vb);
    __nv_bfloat16* o = out + row * KSPLIT + col;
    o[0]   = va;
    o[128] = vb;
    o[256] = __float2bfloat16(r2);
}

__global__ void norm_kernel(const float* __restrict__ cb, float* __restrict__ out, int rows)
{
    int w = (blockIdx.x * blockDim.x + threadIdx.x) >> 5;
    int lane = threadIdx.x & 31;
    if (w >= rows) return;
    const float* r = cb + (size_t)w * CDIM;
    float s = 0.f;
#pragma unroll
    for (int q = 0; q < 4; ++q) { float v = r[lane + q * 32]; s += v * v; }
#pragma unroll
    for (int off = 16; off >= 1; off >>= 1) s += __shfl_xor_sync(0xffffffffu, s, off);
    if (lane == 0) out[w] = s;
}

// ---------------- mma.sync distance + argmin (64-code DB pipeline) ----------
// Per CTA: 128 tokens x 1024 codes. A = ze splits [a|b|c] resident (98KB);
// B = 64-code x 3-plane chunks (49KB), DOUBLE-buffered: next chunk's cp.async
// overlaps current chunk's 512 MMAs/warp. MMA accumulation order per code is
// identical to rounds 7/8 => distances & codes bit-identical.
#define ASTR 784                    // A smem row stride bytes (392 bf16)
#define BSTR 784                    // B smem row stride bytes (392 bf16)
#define DSM_A 0
#define DSM_B (128 * ASTR)          // 100352
#define BBUF (64 * BSTR)            // 50176
#define DSM_BEST (DSM_B + 2 * BBUF) // 200704
#define DSM_TOT (DSM_BEST + 128 * 8)  // 201728

__global__ __launch_bounds__(256, 1) void distMMA_kernel(
    const __nv_bfloat16* __restrict__ zeS,   // [BT_TOK][384]
    const __nv_bfloat16* __restrict__ cbS,   // stage base [CBS][384]
    const float* __restrict__ cbn,           // stage base [CBS]
    unsigned long long* __restrict__ packed)
{
    extern __shared__ char smem[];
    const uint32_t sb = (uint32_t)__cvta_generic_to_shared(smem);
    unsigned long long* sbest = (unsigned long long*)(smem + DSM_BEST);
    const int tid = threadIdx.x;
    const int lane = tid & 31, wid = tid >> 5;
    const int rowband = wid & 3;            // 4 row bands of 32
    const int colhalf = wid >> 2;           // 2 col halves of 32 codes
    const int gid = lane >> 2, tig = lane & 3;
    const int m0 = blockIdx.x * 128;

    if (tid < 128) sbest[tid] = ~0ull;

    // ---- group 0: A (128 x 384 = [a|b|c]) ----
    {
        const __nv_bfloat16* src = zeS + (size_t)m0 * KSPLIT;
#pragma unroll
        for (int it = 0; it < 24; ++it) {
            int idx = tid + it * 256;        // 0..6143
            int row = idx / 48, piece = idx % 48;
            cp16(sb + DSM_A + row * ASTR + piece * 16,
                 src + (size_t)row * KSPLIT + piece * 8);
        }
    }
    CP_COMMIT;
    // ---- group 1: B chunk 0 (codes 0..63, all planes) ----
    {
#pragma unroll
        for (int it = 0; it < 12; ++it) {
            int idx = tid + it * 256;        // 0..3071
            int row = idx / 48, piece = idx % 48;
            cp16(sb + DSM_B + row * BSTR + piece * 16,
                 cbS + (size_t)row * KSPLIT + piece * 8);
        }
    }
    CP_COMMIT;

    // lane-fixed smem addresses
    const uint32_t aBase = sb + DSM_A + (rowband * 32 + (lane & 15)) * ASTR +
                           (lane >> 4) * 16;
    const uint32_t bLaneOff = (colhalf * 32 + (lane & 7)) * BSTR +
                              ((lane >> 3) & 1) * 16;

    float c[2][4][4];
#pragma unroll
    for (int rt = 0; rt < 2; ++rt)
#pragma unroll
        for (int ct = 0; ct < 4; ++ct)
#pragma unroll
            for (int v = 0; v < 4; ++v) c[rt][ct][v] = 0.f;

    for (int nc = 0; nc < 16; ++nc) {
        const int buf = nc & 1;
        if (nc + 1 < 16) {
            // prefetch next chunk into the buffer last read at nc-1
            const __nv_bfloat16* src = cbS + (size_t)(nc + 1) * 64 * KSPLIT;
            const uint32_t dst = sb + DSM_B + (buf ^ 1) * BBUF;
#pragma unroll
            for (int it = 0; it < 12; ++it) {
                int idx = tid + it * 256;
                int row = idx / 48, piece = idx % 48;
                cp16(dst + row * BSTR + piece * 16,
                     src + (size_t)row * KSPLIT + piece * 8);
            }
            CP_COMMIT;
            CP_WAIT1;          // chunk nc resident; nc+1 may stay in flight
        } else {
            CP_WAIT0;
        }
        __syncthreads();

        const uint32_t bBase = sb + DSM_B + buf * BBUF + bLaneOff;
#pragma unroll
        for (int kc = 0; kc < 16; ++kc) {
            const uint32_t aplane = (PA_TAB >> ((kc >> 1) * 4)) & 15;
            const uint32_t bplane = (PB_TAB >> ((kc >> 1) * 4)) & 15;
            const uint32_t abyte = aplane * 256 + (kc & 1) * 128;
            const uint32_t bbyte = bplane * 256 + (kc & 1) * 128;
#pragma unroll
            for (int ks = 0; ks < 4; ++ks) {
                uint32_t a[2][4];
                const uint32_t aoff = abyte + ks * 32;
                LDMX4(a[0], aBase + aoff);
                LDMX4(a[1], aBase + 16 * ASTR + aoff);
                uint32_t b[4][2];
#pragma unroll
                for (int ct = 0; ct < 4; ++ct)
                    LDMX2(b[ct], bBase + ct * 8 * BSTR + bbyte + ks * 32);
#pragma unroll
                for (int rt = 0; rt < 2; ++rt)
#pragma unroll
                    for (int ct = 0; ct < 4; ++ct)
                        MMA16816(c[rt][ct], a[rt], b[ct]);
            }
        }

        // ---- epilogue for this 64-code chunk (same math/keys as R7/R8) ----
        {
            const int ncbase = nc * 64 + colhalf * 32;
#pragma unroll
            for (int rt = 0; rt < 2; ++rt) {
                unsigned long long bl0 = ~0ull, bl1 = ~0ull;
#pragma unroll
                for (int ct = 0; ct < 4; ++ct) {
                    const int n = ncbase + ct * 8 + tig * 2;
                    const float cn0 = cbn[n], cn1 = cbn[n + 1];
                    float d0 = cn0 - 2.0f * c[rt][ct][0];
                    float d1 = cn1 - 2.0f * c[rt][ct][1];
                    float d2 = cn0 - 2.0f * c[rt][ct][2];
                    float d3 = cn1 - 2.0f * c[rt][ct][3];
                    c[rt][ct][0] = 0.f; c[rt][ct][1] = 0.f;
                    c[rt][ct][2] = 0.f; c[rt][ct][3] = 0.f;
                    unsigned i0 = __float_as_uint(d0);
                    unsigned i1 = __float_as_uint(d1);
                    unsigned i2 = __float_as_uint(d2);
                    unsigned i3 = __float_as_uint(d3);
                    i0 ^= (i0 & 0x80000000u) ? 0xffffffffu : 0x80000000u;
                    i1 ^= (i1 & 0x80000000u) ? 0xffffffffu : 0x80000000u;
                    i2 ^= (i2 & 0x80000000u) ? 0xffffffffu : 0x80000000u;
                    i3 ^= (i3 & 0x80000000u) ? 0xffffffffu : 0x80000000u;
                    unsigned long long k0 = ((unsigned long long)i0 << 32) | (unsigned)n;
                    unsigned long long k1 = ((unsigned long long)i1 << 32) | (unsigned)(n + 1);
                    unsigned long long k2 = ((unsigned long long)i2 << 32) | (unsigned)n;
                    unsigned long long k3 = ((unsigned long long)i3 << 32) | (unsigned)(n + 1);
                    if (k1 < k0) k0 = k1;
                    if (k0 < bl0) bl0 = k0;
                    if (k3 < k2) k2 = k3;
                    if (k2 < bl1) bl1 = k2;
                }
#pragma unroll
                for (int off = 1; off <= 2; off <<= 1) {
                    unsigned long long o0 = __shfl_xor_sync(0xffffffffu, bl0, off);
                    unsigned long long o1 = __shfl_xor_sync(0xffffffffu, bl1, off);
                    if (o0 < bl0) bl0 = o0;
                    if (o1 < bl1) bl1 = o1;
                }
                if (tig == 0) {
                    const int rbase = rowband * 32 + rt * 16 + gid;
                    atomicMin(&sbest[rbase], bl0);
                    atomicMin(&sbest[rbase + 8], bl1);
                }
            }
        }
        __syncthreads();   // retire all readers of buf before its overwrite
    }

    if (tid < 128) packed[m0 + tid] = sbest[tid];
}

// ---------------- per-token fused epilogue ----------------------------------
__global__ __launch_bounds__(128) void fused_update_kernel(
    const float* __restrict__ Ze, const float* __restrict__ cb,
    const float* __restrict__ G, const unsigned long long* __restrict__ packed,
    float* __restrict__ out_codes, int stage, float* __restrict__ partial,
    float* __restrict__ R)
{
    __shared__ float red[128];
    const int t = blockIdx.x;
    const int tid = threadIdx.x;
    const unsigned idx = (unsigned)(packed[t] & 0xffffffffu);

    float d = Ze[(size_t)t * CDIM + tid] - cb[(size_t)idx * CDIM + tid];
    red[tid] = d * d;
    __syncthreads();
#pragma unroll
    for (int st = 64; st > 0; st >>= 1) {
        if (tid < st) red[tid] += red[tid + st];
        __syncthreads();
    }
    if (tid == 0) {
        partial[t] = red[0];
        out_codes[(size_t)t * NCB + stage] = (float)idx;
    }

    float4* R4 = (float4*)(R + (size_t)t * ENC);
    const float4* G4 = (const float4*)(G + (size_t)idx * ENC);
    float4 r = R4[tid];
    float4 g = G4[tid];
    r.x -= g.x; r.y -= g.y; r.z -= g.z; r.w -= g.w;
    R4[tid] = r;
}

__global__ void final_loss_kernel(const float* __restrict__ partial, float* __restrict__ out)
{
    __shared__ float s[256];
    float v = 0.f;
    const int per = (NCB * BT_TOK) / 256;   // 1024
    for (int q = 0; q < per; ++q) v += partial[threadIdx.x * per + q];
    s[threadIdx.x] = v;
    __syncthreads();
    for (int st = 128; st > 0; st >>= 1) {
        if (threadIdx.x < st) s[threadIdx.x] += s[threadIdx.x + st];
        __syncthreads();
    }
    if (threadIdx.x == 0)
        out[(size_t)BT_TOK * NCB] = 1.25f * s[0] / (float)((size_t)BT_TOK * CDIM);
}

// ---------------- launch ----------------------------------------------------
extern "C" void kernel_launch(void* const* d_in, const int* in_sizes, int n_in,
                              void* d_out, int out_size)
{
    const float* z    = (const float*)d_in[0];   // (16,2048,768)
    const float* Win  = (const float*)d_in[1];   // (768,512)
    const float* bin  = (const float*)d_in[2];   // (512,)
    const float* cbs  = (const float*)d_in[3];   // (8,1024,128)
    const float* inw  = (const float*)d_in[4];   // (8,512,128)
    const float* outw = (const float*)d_in[5];   // (8,128,512)
    float* out = (float*)d_out;

    float *gR, *gZe, *gCbn, *gLP, *gG;
    __nv_bfloat16 *gZeS, *gCbS;
    unsigned long long* gPk;
    cudaGetSymbolAddress((void**)&gR,   g_R);
    cudaGetSymbolAddress((void**)&gZe,  g_Ze);
    cudaGetSymbolAddress((void**)&gZeS, g_zeS);
    cudaGetSymbolAddress((void**)&gCbS, g_cbS);
    cudaGetSymbolAddress((void**)&gCbn, g_cbnorm);
    cudaGetSymbolAddress((void**)&gLP,  g_lossPartial);
    cudaGetSymbolAddress((void**)&gG,   g_G);
    cudaGetSymbolAddress((void**)&gPk,  g_packed);

    cudaFuncSetAttribute(distMMA_kernel,
                         cudaFuncAttributeMaxDynamicSharedMemorySize, DSM_TOT);

    // 1. residual = z @ W_in + b_in
    sgemm4<true, false><<<dim3(BT_TOK / 128, ENC / 128, 1), 256>>>(
        z, Win, gR, bin, nullptr, IN_DIM, ENC, 0, 0, 0);

    // 2. codebook norms + exact bf16x3 splits ([a|b|c] layout)
    norm_kernel<<<(NCB * CBS * 32) / 256, 256>>>(cbs, gCbn, NCB * CBS);
    split_cb_kernel<<<(NCB * CBS * CDIM) / 256, 256>>>(cbs, gCbS);

    // 3. dec tables: G_i = cb_i @ out_w_i (batched over blockIdx.z)
    sgemm4<false, false><<<dim3(CBS / 128, ENC / 128, NCB), 256>>>(
        cbs, outw, gG, nullptr, nullptr, CDIM, ENC,
        (size_t)CBS * CDIM, (size_t)CDIM * ENC, (size_t)CBS * ENC);

    for (int i = 0; i < NCB; ++i) {
        const float* cb_i = cbs + (size_t)i * CBS * CDIM;

        // z_e = R @ in_w[i]  (fp32 + exact bf16x3 splits)
        sgemm4<false, true><<<dim3(BT_TOK / 128, CDIM / 128, 1), 256>>>(
            gR, inw + (size_t)i * ENC * CDIM, gZe, nullptr, gZeS, ENC, CDIM, 0, 0, 0);

        // distances + argmin on tensor cores (8 plane-pair passes, bit-identical)
        distMMA_kernel<<<BT_TOK / 128, 256, DSM_TOT>>>(
            gZeS, gCbS + (size_t)i * CBS * KSPLIT, gCbn + (size_t)i * CBS, gPk);

        // codes + loss partials + R -= G[idx]
        fused_update_kernel<<<BT_TOK, 128>>>(
            gZe, cb_i, gG + (size_t)i * CBS * ENC, gPk, out, i,
            gLP + (size_t)i * BT_TOK, gR);
    }

    final_loss_kernel<<<1, 256>>>(gLP, out);
}

// round 10
// speedup vs baseline: 1.3497x; 1.1976x over previous
#include <cuda_runtime.h>
#include <cuda_bf16.h>
#include <cstdint>

#define BT_TOK 32768      // B*T = 16*2048
#define IN_DIM 768
#define ENC 512
#define CDIM 128
#define NCB 8
#define CBS 1024
#define KS2 256           // 2 exact bf16 split planes [a|b] per row

// ---------------- scratch (static device globals; no allocations) ----------
__device__ float g_R[BT_TOK * ENC];                    // residual (64MB)
__device__ float g_Ze[BT_TOK * CDIM];                  // z_e fp32 (16MB)
__device__ __nv_bfloat16 g_zeS[(size_t)BT_TOK * KS2];  // ze splits (17MB)
__device__ __nv_bfloat16 g_cbS[(size_t)NCB * CBS * KS2]; // cb splits (4MB)
__device__ float g_D[(size_t)BT_TOK * CBS];            // approx distances (128MB)
__device__ unsigned long long g_packed[BT_TOK];        // (distkey<<32)|idx
__device__ float g_cbnorm[NCB * CBS];                  // ||c||^2
__device__ unsigned g_maxC2u[NCB];                     // max ||c||^2 (bits), zero-init
__device__ float g_G[NCB * CBS * ENC];                 // cb @ out_w tables (16MB)
__device__ float g_lossPartial[NCB * BT_TOK];          // deterministic partials

// ---------------- helpers ----------------------------------------------------
__device__ __forceinline__ void cp16(uint32_t smem, const void* gmem) {
    asm volatile("cp.async.cg.shared.global [%0], [%1], 16;\n" :: "r"(smem), "l"(gmem));
}
__device__ __forceinline__ void cp16p(void* smem, const void* gmem) {
    cp16((uint32_t)__cvta_generic_to_shared(smem), gmem);
}
#define CP_COMMIT asm volatile("cp.async.commit_group;\n" ::)
#define CP_WAIT0  asm volatile("cp.async.wait_group 0;\n" ::)
#define CP_WAIT1  asm volatile("cp.async.wait_group 1;\n" ::)

__device__ __forceinline__ unsigned long long pack2(float lo, float hi) {
    unsigned long long r;
    asm("mov.b64 %0, {%1, %2};" : "=l"(r) : "f"(lo), "f"(hi));
    return r;
}
__device__ __forceinline__ void unpack2(float& lo, float& hi, unsigned long long v) {
    asm("mov.b64 {%0, %1}, %2;" : "=f"(lo), "=f"(hi) : "l"(v));
}
__device__ __forceinline__ void fma2(unsigned long long& d, unsigned long long a,
                                     unsigned long long b) {
    asm("fma.rn.f32x2 %0, %1, %2, %0;" : "+l"(d) : "l"(a), "l"(b));
}

#define LDMX4(r, addr) \
    asm volatile("ldmatrix.sync.aligned.m8n8.x4.shared.b16 {%0,%1,%2,%3}, [%4];" \
                 : "=r"((r)[0]), "=r"((r)[1]), "=r"((r)[2]), "=r"((r)[3]) : "r"(addr))
#define LDMX2(r, addr) \
    asm volatile("ldmatrix.sync.aligned.m8n8.x2.shared.b16 {%0,%1}, [%2];" \
                 : "=r"((r)[0]), "=r"((r)[1]) : "r"(addr))
#define MMA16816(c, a, b) \
    asm volatile("mma.sync.aligned.m16n8k16.row.col.f32.bf16.bf16.f32 " \
                 "{%0,%1,%2,%3}, {%4,%5,%6,%7}, {%8,%9}, {%0,%1,%2,%3};" \
                 : "+f"((c)[0]), "+f"((c)[1]), "+f"((c)[2]), "+f"((c)[3]) \
                 : "r"((a)[0]), "r"((a)[1]), "r"((a)[2]), "r"((a)[3]), \
                   "r"((b)[0]), "r"((b)[1]))

// ---------------- SGEMM: 128x128 tile, BK=16, smem DB, FFMA2 core ----------
// C = A @ B (+bias). SPLIT: also emit exact bf16x2 decomposition of C ([a|b]).
// Per-output fp32 accumulation chain: k strictly ascending (bit-identical R1-R9).
template<bool BIAS, bool SPLIT>
__global__ __launch_bounds__(256, 2) void sgemm4(
    const float* __restrict__ A, const float* __restrict__ B,
    float* __restrict__ C, const float* __restrict__ bias,
    __nv_bfloat16* __restrict__ splitOut, int K, int N,
    size_t strA, size_t strB, size_t strC)
{
    __shared__ float As[2][16][128];
    __shared__ float Bs[2][16][128];
    A += (size_t)blockIdx.z * strA;
    B += (size_t)blockIdx.z * strB;
    C += (size_t)blockIdx.z * strC;
    const int tid = threadIdx.x;
    const int tx = tid & 15, ty = tid >> 4;
    const int m0 = blockIdx.x * 128;
    const int n0 = blockIdx.y * 128;

    const int ar = tid & 127;
    const int ah = (tid >> 7) * 8;
    const int br = tid >> 4;
    const int bc = (tid & 15) * 4;

    const float* aptr = A + (size_t)(m0 + ar) * K;
    const float* bptr = B + n0;

    const int T = K >> 4;

    float4 av0 = *(const float4*)(aptr + ah);
    float4 av1 = *(const float4*)(aptr + ah + 4);
    cp16p(&Bs[0][br][bc],      bptr + (size_t)br * N + bc);
    cp16p(&Bs[0][br][bc + 64], bptr + (size_t)br * N + bc + 64);
    As[0][ah + 0][ar] = av0.x; As[0][ah + 1][ar] = av0.y;
    As[0][ah + 2][ar] = av0.z; As[0][ah + 3][ar] = av0.w;
    As[0][ah + 4][ar] = av1.x; As[0][ah + 5][ar] = av1.y;
    As[0][ah + 6][ar] = av1.z; As[0][ah + 7][ar] = av1.w;
    CP_COMMIT;
    CP_WAIT0;
    __syncthreads();

    unsigned long long acc2[8][4];
#pragma unroll
    for (int i = 0; i < 8; ++i)
#pragma unroll
        for (int j = 0; j < 4; ++j) acc2[i][j] = 0ull;

    for (int t = 0; t < T; ++t) {
        const int buf = t & 1;
        const bool pf = (t + 1 < T);
        const int kn = (t + 1) << 4;
        if (pf) {
            av0 = *(const float4*)(aptr + kn + ah);
            av1 = *(const float4*)(aptr + kn + ah + 4);
            cp16p(&Bs[buf ^ 1][br][bc],      bptr + (size_t)(kn + br) * N + bc);
            cp16p(&Bs[buf ^ 1][br][bc + 64], bptr + (size_t)(kn + br) * N + bc + 64);
            CP_COMMIT;
        }
#pragma unroll
        for (int k = 0; k < 16; ++k) {
            float a[8];
            *(float4*)(a)     = *(const float4*)&As[buf][k][ty * 8];
            *(float4*)(a + 4) = *(const float4*)&As[buf][k][ty * 8 + 4];
            float4 b0 = *(const float4*)&Bs[buf][k][tx * 8];
            float4 b1 = *(const float4*)&Bs[buf][k][tx * 8 + 4];
            unsigned long long bb[4];
            bb[0] = pack2(b0.x, b0.y); bb[1] = pack2(b0.z, b0.w);
            bb[2] = pack2(b1.x, b1.y); bb[3] = pack2(b1.z, b1.w);
#pragma unroll
            for (int i = 0; i < 8; ++i) {
                unsigned long long ai = pack2(a[i], a[i]);
#pragma unroll
                for (int j = 0; j < 4; ++j) fma2(acc2[i][j], ai, bb[j]);
            }
        }
        if (pf) {
            As[buf ^ 1][ah + 0][ar] = av0.x; As[buf ^ 1][ah + 1][ar] = av0.y;
            As[buf ^ 1][ah + 2][ar] = av0.z; As[buf ^ 1][ah + 3][ar] = av0.w;
            As[buf ^ 1][ah + 4][ar] = av1.x; As[buf ^ 1][ah + 5][ar] = av1.y;
            As[buf ^ 1][ah + 6][ar] = av1.z; As[buf ^ 1][ah + 7][ar] = av1.w;
            CP_WAIT0;
            __syncthreads();
        }
    }

#pragma unroll
    for (int i = 0; i < 8; ++i) {
        float c[8];
#pragma unroll
        for (int j = 0; j < 4; ++j) unpack2(c[2 * j], c[2 * j + 1], acc2[i][j]);
        int m = m0 + ty * 8 + i;
        float* crow = C + (size_t)m * N + n0 + tx * 8;
        if (BIAS) {
#pragma unroll
            for (int j = 0; j < 8; ++j) crow[j] = c[j] + bias[n0 + tx * 8 + j];
        } else {
#pragma unroll
            for (int j = 0; j < 8; ++j) crow[j] = c[j];
        }
        if (SPLIT) {
            __align__(16) __nv_bfloat16 pa[8], pb[8];
#pragma unroll
            for (int j = 0; j < 8; ++j) {
                float x = c[j];
                __nv_bfloat16 va = __float2bfloat16(x);
                float r1 = x - __bfloat162float(va);
                pa[j] = va; pb[j] = __float2bfloat16(r1);
            }
            size_t off = (size_t)m * KS2 + n0 + tx * 8;
            *(uint4*)(splitOut + off)       = *(const uint4*)pa;
            *(uint4*)(splitOut + off + 128) = *(const uint4*)pb;
        }
    }
}

// ---------------- codebook split + norms -----------------------------------
__global__ void split_cb_kernel(const float* __restrict__ cb,
                                __nv_bfloat16* __restrict__ out)
{
    size_t i = (size_t)blockIdx.x * blockDim.x + threadIdx.x;
    if (i >= (size_t)NCB * CBS * CDIM) return;
    size_t row = i >> 7;
    int col = (int)(i & 127);
    float x = cb[i];
    __nv_bfloat16 va = __float2bfloat16(x);
    float r1 = x - __bfloat162float(va);
    __nv_bfloat16* o = out + row * KS2 + col;
    o[0]   = va;
    o[128] = __float2bfloat16(r1);
}

// norms + per-stage max||c||^2 (atomicMax on positive-float bits: order-free)
__global__ void norm_kernel(const float* __restrict__ cb, float* __restrict__ out,
                            unsigned* __restrict__ maxC2u, int rows)
{
    int w = (blockIdx.x * blockDim.x + threadIdx.x) >> 5;
    int lane = threadIdx.x & 31;
    if (w >= rows) return;
    const float* r = cb + (size_t)w * CDIM;
    float s = 0.f;
#pragma unroll
    for (int q = 0; q < 4; ++q) { float v = r[lane + q * 32]; s += v * v; }
#pragma unroll
    for (int off = 16; off >= 1; off >>= 1) s += __shfl_xor_sync(0xffffffffu, s, off);
    if (lane == 0) {
        out[w] = s;
        atomicMax(&maxC2u[w >> 10], __float_as_uint(s));
    }
}

// ---------------- phase 1: approximate distances via 3-pass bf16 MMA --------
// Per CTA: 128 tokens x 1024 codes. A = ze splits [a|b] resident (66KB);
// B = 64-code [a|b] chunks (33KB) double-buffered. Passes (aa, ab, ba);
// d~ = ||c||^2 - 2*acc written to g_D. Error certified <= 2^-12.6*||z||*maxC.
#define A2STR 528                      // row stride bytes (264 bf16; 528/16 odd)
#define P1_B (128 * A2STR)             // 67584
#define P1_BBUF (64 * A2STR)           // 33792
#define P1_TOT (P1_B + 2 * P1_BBUF)    // 135168

__global__ __launch_bounds__(256, 1) void distApprox_kernel(
    const __nv_bfloat16* __restrict__ zeS,   // [BT_TOK][256]
    const __nv_bfloat16* __restrict__ cbS,   // stage base [CBS][256]
    const float* __restrict__ cbn,           // stage base [CBS]
    float* __restrict__ D)                   // [BT_TOK][CBS]
{
    extern __shared__ char smem[];
    const uint32_t sb = (uint32_t)__cvta_generic_to_shared(smem);
    const int tid = threadIdx.x;
    const int lane = tid & 31, wid = tid >> 5;
    const int rowband = wid & 3;
    const int colhalf = wid >> 2;
    const int gid = lane >> 2, tig = lane & 3;
    const int m0 = blockIdx.x * 128;

    // A: 128 rows x 512B
    {
        const __nv_bfloat16* src = zeS + (size_t)m0 * KS2;
#pragma unroll
        for (int it = 0; it < 16; ++it) {
            int idx = tid + it * 256;
            int row = idx >> 5, piece = idx & 31;
            cp16(sb + row * A2STR + piece * 16, src + (size_t)row * KS2 + piece * 8);
        }
    }
    CP_COMMIT;
    // B chunk 0
    {
#pragma unroll
        for (int it = 0; it < 8; ++it) {
            int idx = tid + it * 256;
            int row = idx >> 5, piece = idx & 31;
            cp16(sb + P1_B + row * A2STR + piece * 16,
                 cbS + (size_t)row * KS2 + piece * 8);
        }
    }
    CP_COMMIT;

    const uint32_t aBase = sb + (rowband * 32 + (lane & 15)) * A2STR + (lane >> 4) * 16;
    const uint32_t bLaneOff = (colhalf * 32 + (lane & 7)) * A2STR +
                              ((lane >> 3) & 1) * 16;

    float c[2][4][4];
#pragma unroll
    for (int rt = 0; rt < 2; ++rt)
#pragma unroll
        for (int ct = 0; ct < 4; ++ct)
#pragma unroll
            for (int v = 0; v < 4; ++v) c[rt][ct][v] = 0.f;

    for (int nc = 0; nc < 16; ++nc) {
        const int buf = nc & 1;
        if (nc + 1 < 16) {
            const __nv_bfloat16* src = cbS + (size_t)(nc + 1) * 64 * KS2;
            const uint32_t dst = sb + P1_B + (buf ^ 1) * P1_BBUF;
#pragma unroll
            for (int it = 0; it < 8; ++it) {
                int idx = tid + it * 256;
                int row = idx >> 5, piece = idx & 31;
                cp16(dst + row * A2STR + piece * 16,
                     src + (size_t)row * KS2 + piece * 8);
            }
            CP_COMMIT;
            CP_WAIT1;
        } else {
            CP_WAIT0;
        }
        __syncthreads();

        const uint32_t bBase = sb + P1_B + buf * P1_BBUF + bLaneOff;
#pragma unroll
        for (int kc = 0; kc < 6; ++kc) {
            const int p = kc >> 1;
            const uint32_t aoff = ((p == 2) ? 256u : 0u) + (kc & 1) * 128;
            const uint32_t boff = ((p == 1) ? 256u : 0u) + (kc & 1) * 128;
#pragma unroll
            for (int ks = 0; ks < 4; ++ks) {
                uint32_t a[2][4];
                LDMX4(a[0], aBase + aoff + ks * 32);
                LDMX4(a[1], aBase + 16 * A2STR + aoff + ks * 32);
                uint32_t b[4][2];
#pragma unroll
                for (int ct = 0; ct < 4; ++ct)
                    LDMX2(b[ct], bBase + ct * 8 * A2STR + boff + ks * 32);
#pragma unroll
                for (int rt = 0; rt < 2; ++rt)
#pragma unroll
                    for (int ct = 0; ct < 4; ++ct)
                        MMA16816(c[rt][ct], a[rt], b[ct]);
            }
        }

        // write approx distances for this 64-code chunk
        {
            const int colb = nc * 64 + colhalf * 32;
#pragma unroll
            for (int rt = 0; rt < 2; ++rt) {
                const int row = m0 + rowband * 32 + rt * 16 + gid;
                float* d0 = D + (size_t)row * CBS;
                float* d1 = D + (size_t)(row + 8) * CBS;
#pragma unroll
                for (int ct = 0; ct < 4; ++ct) {
                    const int col = colb + ct * 8 + tig * 2;
                    const float cn0 = cbn[col], cn1 = cbn[col + 1];
                    float2 v0, v1;
                    v0.x = cn0 - 2.0f * c[rt][ct][0];
                    v0.y = cn1 - 2.0f * c[rt][ct][1];
                    v1.x = cn0 - 2.0f * c[rt][ct][2];
                    v1.y = cn1 - 2.0f * c[rt][ct][3];
                    *(float2*)(d0 + col) = v0;
                    *(float2*)(d1 + col) = v1;
                    c[rt][ct][0] = 0.f; c[rt][ct][1] = 0.f;
                    c[rt][ct][2] = 0.f; c[rt][ct][3] = 0.f;
                }
            }
        }
        __syncthreads();
    }
}

// ---------------- phase 2: certified candidate rescore (exact fp32) ---------
// Per warp = 1 token. Find min approx distance; rescore all codes within
// margin M = 2^-9*||ze||*maxC (rigorous bound >= 2x the worst-case approx
// error) using the SAME fp32 chain as R4: acc = fma(ze_k, cb_k, acc), k asc;
// d = cbn - 2*acc; min of (monotonic(d)<<32 | n). Guaranteed == full argmin.
__global__ __launch_bounds__(256) void argminExact_kernel(
    const float* __restrict__ Ze, const float* __restrict__ D,
    const float* __restrict__ cb, const float* __restrict__ cbn,
    const unsigned* __restrict__ maxC2u, int stage,
    unsigned long long* __restrict__ packed)
{
    __shared__ float zrow[8][128];
    const int lane = threadIdx.x & 31, wid = threadIdx.x >> 5;
    const int t = blockIdx.x * 8 + wid;

    const float* zep = Ze + (size_t)t * CDIM;
    float zn2 = 0.f;
#pragma unroll
    for (int q = 0; q < 4; ++q) {
        float v = zep[lane + q * 32];
        zrow[wid][lane + q * 32] = v;
        zn2 += v * v;
    }
#pragma unroll
    for (int off = 16; off >= 1; off >>= 1)
        zn2 += __shfl_xor_sync(0xffffffffu, zn2, off);
    __syncwarp();

    const float margin = ldexpf(sqrtf(zn2 * __uint_as_float(maxC2u[stage])), -9);
    const float* drow = D + (size_t)t * CBS;

    float dmin = 3.4e38f;
#pragma unroll 8
    for (int i = 0; i < 32; ++i)
        dmin = fminf(dmin, drow[i * 32 + lane]);
#pragma unroll
    for (int off = 16; off >= 1; off >>= 1)
        dmin = fminf(dmin, __shfl_xor_sync(0xffffffffu, dmin, off));

    const float thr = dmin + margin;
    unsigned long long best = ~0ull;
    for (int i = 0; i < 32; ++i) {
        float d = drow[i * 32 + lane];
        if (d <= thr) {
            const int n = i * 32 + lane;
            const float* cr = cb + (size_t)n * CDIM;
            float acc = 0.f;
#pragma unroll 16
            for (int k = 0; k < 128; ++k)
                acc = fmaf(zrow[wid][k], cr[k], acc);
            float dd = cbn[n] - 2.0f * acc;
            unsigned ib = __float_as_uint(dd);
            ib ^= (ib & 0x80000000u) ? 0xffffffffu : 0x80000000u;
            unsigned long long key = ((unsigned long long)ib << 32) | (unsigned)n;
            if (key < best) best = key;
        }
    }
#pragma unroll
    for (int off = 16; off >= 1; off >>= 1) {
        unsigned long long o = __shfl_xor_sync(0xffffffffu, best, off);
        if (o < best) best = o;
    }
    if (lane == 0) packed[t] = best;
}

// ---------------- per-token fused epilogue ----------------------------------
__global__ __launch_bounds__(128) void fused_update_kernel(
    const float* __restrict__ Ze, const float* __restrict__ cb,
    const float* __restrict__ G, const unsigned long long* __restrict__ packed,
    float* __restrict__ out_codes, int stage, float* __restrict__ partial,
    float* __restrict__ R)
{
    __shared__ float red[128];
    const int t = blockIdx.x;
    const int tid = threadIdx.x;
    const unsigned idx = (unsigned)(packed[t] & 0xffffffffu);

    float d = Ze[(size_t)t * CDIM + tid] - cb[(size_t)idx * CDIM + tid];
    red[tid] = d * d;
    __syncthreads();
#pragma unroll
    for (int st = 64; st > 0; st >>= 1) {
        if (tid < st) red[tid] += red[tid + st];
        __syncthreads();
    }
    if (tid == 0) {
        partial[t] = red[0];
        out_codes[(size_t)t * NCB + stage] = (float)idx;
    }

    float4* R4 = (float4*)(R + (size_t)t * ENC);
    const float4* G4 = (const float4*)(G + (size_t)idx * ENC);
    float4 r = R4[tid];
    float4 g = G4[tid];
    r.x -= g.x; r.y -= g.y; r.z -= g.z; r.w -= g.w;
    R4[tid] = r;
}

__global__ void final_loss_kernel(const float* __restrict__ partial, float* __restrict__ out)
{
    __shared__ float s[256];
    float v = 0.f;
    const int per = (NCB * BT_TOK) / 256;   // 1024
    for (int q = 0; q < per; ++q) v += partial[threadIdx.x * per + q];
    s[threadIdx.x] = v;
    __syncthreads();
    for (int st = 128; st > 0; st >>= 1) {
        if (threadIdx.x < st) s[threadIdx.x] += s[threadIdx.x + st];
        __syncthreads();
    }
    if (threadIdx.x == 0)
        out[(size_t)BT_TOK * NCB] = 1.25f * s[0] / (float)((size_t)BT_TOK * CDIM);
}

// ---------------- launch ----------------------------------------------------
extern "C" void kernel_launch(void* const* d_in, const int* in_sizes, int n_in,
                              void* d_out, int out_size)
{
    const float* z    = (const float*)d_in[0];   // (16,2048,768)
    const float* Win  = (const float*)d_in[1];   // (768,512)
    const float* bin  = (const float*)d_in[2];   // (512,)
    const float* cbs  = (const float*)d_in[3];   // (8,1024,128)
    const float* inw  = (const float*)d_in[4];   // (8,512,128)
    const float* outw = (const float*)d_in[5];   // (8,128,512)
    float* out = (float*)d_out;

    float *gR, *gZe, *gCbn, *gLP, *gG, *gD;
    __nv_bfloat16 *gZeS, *gCbS;
    unsigned long long* gPk;
    unsigned* gMx;
    cudaGetSymbolAddress((void**)&gR,   g_R);
    cudaGetSymbolAddress((void**)&gZe,  g_Ze);
    cudaGetSymbolAddress((void**)&gZeS, g_zeS);
    cudaGetSymbolAddress((void**)&gCbS, g_cbS);
    cudaGetSymbolAddress((void**)&gCbn, g_cbnorm);
    cudaGetSymbolAddress((void**)&gMx,  g_maxC2u);
    cudaGetSymbolAddress((void**)&gLP,  g_lossPartial);
    cudaGetSymbolAddress((void**)&gG,   g_G);
    cudaGetSymbolAddress((void**)&gPk,  g_packed);
    cudaGetSymbolAddress((void**)&gD,   g_D);

    cudaFuncSetAttribute(distApprox_kernel,
                         cudaFuncAttributeMaxDynamicSharedMemorySize, P1_TOT);

    // 1. residual = z @ W_in + b_in
    sgemm4<true, false><<<dim3(BT_TOK / 128, ENC / 128, 1), 256>>>(
        z, Win, gR, bin, nullptr, IN_DIM, ENC, 0, 0, 0);

    // 2. codebook norms (+ per-stage max) + exact bf16x2 splits
    norm_kernel<<<(NCB * CBS * 32) / 256, 256>>>(cbs, gCbn, gMx, NCB * CBS);
    split_cb_kernel<<<(NCB * CBS * CDIM) / 256, 256>>>(cbs, gCbS);

    // 3. dec tables: G_i = cb_i @ out_w_i (batched over blockIdx.z)
    sgemm4<false, false><<<dim3(CBS / 128, ENC / 128, NCB), 256>>>(
        cbs, outw, gG, nullptr, nullptr, CDIM, ENC,
        (size_t)CBS * CDIM, (size_t)CDIM * ENC, (size_t)CBS * ENC);

    for (int i = 0; i < NCB; ++i) {
        const float* cb_i = cbs + (size_t)i * CBS * CDIM;

        // z_e = R @ in_w[i]  (fp32 + exact bf16x2 splits)
        sgemm4<false, true><<<dim3(BT_TOK / 128, CDIM / 128, 1), 256>>>(
            gR, inw + (size_t)i * ENC * CDIM, gZe, nullptr, gZeS, ENC, CDIM, 0, 0, 0);

        // phase 1: approx distances (3-pass bf16 split MMA)
        distApprox_kernel<<<BT_TOK / 128, 256, P1_TOT>>>(
            gZeS, gCbS + (size_t)i * CBS * KS2, gCbn + (size_t)i * CBS, gD);

        // phase 2: certified exact fp32 argmin over margin candidates
        argminExact_kernel<<<BT_TOK / 8, 256>>>(
            gZe, gD, cb_i, gCbn + (size_t)i * CBS, gMx, i, gPk);

        // codes + loss partials + R -= G[idx]
        fused_update_kernel<<<BT_TOK, 128>>>(
            gZe, cb_i, gG + (size_t)i * CBS * ENC, gPk, out, i,
            gLP + (size_t)i * BT_TOK, gR);
    }

    final_loss_kernel<<<1, 256>>>(gLP, out);
}

// round 11
// speedup vs baseline: 1.5297x; 1.1334x over previous
#include <cuda_runtime.h>
#include <cuda_bf16.h>
#include <cuda_fp16.h>
#include <cstdint>

#define BT_TOK 32768      // B*T = 16*2048
#define IN_DIM 768
#define ENC 512
#define CDIM 128
#define NCB 8
#define CBS 1024

// ---------------- scratch (static device globals; no allocations) ----------
__device__ float g_R[BT_TOK * ENC];                    // residual (64MB)
__device__ float g_Ze[BT_TOK * CDIM];                  // z_e fp32 (16MB)
__device__ __nv_bfloat16 g_zeA[(size_t)BT_TOK * CDIM]; // ze bf16 a-plane (8MB)
__device__ __nv_bfloat16 g_cbA[(size_t)NCB * CBS * CDIM]; // cb a-plane (2MB)
__device__ __half g_D[(size_t)BT_TOK * CBS];           // approx distances (64MB)
__device__ unsigned long long g_packed[BT_TOK];        // (distkey<<32)|idx
__device__ float g_cbnorm[NCB * CBS];                  // ||c||^2
__device__ unsigned g_maxC2u[NCB];                     // max ||c||^2 (bits), zero-init
__device__ float g_G[NCB * CBS * ENC];                 // cb @ out_w tables (16MB)
__device__ float g_lossPartial[NCB * BT_TOK];          // deterministic partials

// ---------------- helpers ----------------------------------------------------
__device__ __forceinline__ void cp16(uint32_t smem, const void* gmem) {
    asm volatile("cp.async.cg.shared.global [%0], [%1], 16;\n" :: "r"(smem), "l"(gmem));
}
__device__ __forceinline__ void cp16p(void* smem, const void* gmem) {
    cp16((uint32_t)__cvta_generic_to_shared(smem), gmem);
}
#define CP_COMMIT asm volatile("cp.async.commit_group;\n" ::)
#define CP_WAIT0  asm volatile("cp.async.wait_group 0;\n" ::)
#define CP_WAIT1  asm volatile("cp.async.wait_group 1;\n" ::)

__device__ __forceinline__ unsigned long long pack2(float lo, float hi) {
    unsigned long long r;
    asm("mov.b64 %0, {%1, %2};" : "=l"(r) : "f"(lo), "f"(hi));
    return r;
}
__device__ __forceinline__ void unpack2(float& lo, float& hi, unsigned long long v) {
    asm("mov.b64 {%0, %1}, %2;" : "=f"(lo), "=f"(hi) : "l"(v));
}
__device__ __forceinline__ void fma2(unsigned long long& d, unsigned long long a,
                                     unsigned long long b) {
    asm("fma.rn.f32x2 %0, %1, %2, %0;" : "+l"(d) : "l"(a), "l"(b));
}

#define LDMX4(r, addr) \
    asm volatile("ldmatrix.sync.aligned.m8n8.x4.shared.b16 {%0,%1,%2,%3}, [%4];" \
                 : "=r"((r)[0]), "=r"((r)[1]), "=r"((r)[2]), "=r"((r)[3]) : "r"(addr))
#define LDMX2(r, addr) \
    asm volatile("ldmatrix.sync.aligned.m8n8.x2.shared.b16 {%0,%1}, [%2];" \
                 : "=r"((r)[0]), "=r"((r)[1]) : "r"(addr))
#define MMA16816(c, a, b) \
    asm volatile("mma.sync.aligned.m16n8k16.row.col.f32.bf16.bf16.f32 " \
                 "{%0,%1,%2,%3}, {%4,%5,%6,%7}, {%8,%9}, {%0,%1,%2,%3};" \
                 : "+f"((c)[0]), "+f"((c)[1]), "+f"((c)[2]), "+f"((c)[3]) \
                 : "r"((a)[0]), "r"((a)[1]), "r"((a)[2]), "r"((a)[3]), \
                   "r"((b)[0]), "r"((b)[1]))

// ---------------- SGEMM: 128x128 tile, BK=16, smem DB, FFMA2 core ----------
// C = A @ B (+bias). SPLIT: also emit bf16 a-plane of C.
// Per-output fp32 accumulation chain: k strictly ascending (bit-identical R1-R10).
template<bool BIAS, bool SPLIT>
__global__ __launch_bounds__(256, 2) void sgemm4(
    const float* __restrict__ A, const float* __restrict__ B,
    float* __restrict__ C, const float* __restrict__ bias,
    __nv_bfloat16* __restrict__ splitOut, int K, int N,
    size_t strA, size_t strB, size_t strC)
{
    __shared__ float As[2][16][128];
    __shared__ float Bs[2][16][128];
    A += (size_t)blockIdx.z * strA;
    B += (size_t)blockIdx.z * strB;
    C += (size_t)blockIdx.z * strC;
    const int tid = threadIdx.x;
    const int tx = tid & 15, ty = tid >> 4;
    const int m0 = blockIdx.x * 128;
    const int n0 = blockIdx.y * 128;

    const int ar = tid & 127;
    const int ah = (tid >> 7) * 8;
    const int br = tid >> 4;
    const int bc = (tid & 15) * 4;

    const float* aptr = A + (size_t)(m0 + ar) * K;
    const float* bptr = B + n0;

    const int T = K >> 4;

    float4 av0 = *(const float4*)(aptr + ah);
    float4 av1 = *(const float4*)(aptr + ah + 4);
    cp16p(&Bs[0][br][bc],      bptr + (size_t)br * N + bc);
    cp16p(&Bs[0][br][bc + 64], bptr + (size_t)br * N + bc + 64);
    As[0][ah + 0][ar] = av0.x; As[0][ah + 1][ar] = av0.y;
    As[0][ah + 2][ar] = av0.z; As[0][ah + 3][ar] = av0.w;
    As[0][ah + 4][ar] = av1.x; As[0][ah + 5][ar] = av1.y;
    As[0][ah + 6][ar] = av1.z; As[0][ah + 7][ar] = av1.w;
    CP_COMMIT;
    CP_WAIT0;
    __syncthreads();

    unsigned long long acc2[8][4];
#pragma unroll
    for (int i = 0; i < 8; ++i)
#pragma unroll
        for (int j = 0; j < 4; ++j) acc2[i][j] = 0ull;

    for (int t = 0; t < T; ++t) {
        const int buf = t & 1;
        const bool pf = (t + 1 < T);
        const int kn = (t + 1) << 4;
        if (pf) {
            av0 = *(const float4*)(aptr + kn + ah);
            av1 = *(const float4*)(aptr + kn + ah + 4);
            cp16p(&Bs[buf ^ 1][br][bc],      bptr + (size_t)(kn + br) * N + bc);
            cp16p(&Bs[buf ^ 1][br][bc + 64], bptr + (size_t)(kn + br) * N + bc + 64);
            CP_COMMIT;
        }
#pragma unroll
        for (int k = 0; k < 16; ++k) {
            float a[8];
            *(float4*)(a)     = *(const float4*)&As[buf][k][ty * 8];
            *(float4*)(a + 4) = *(const float4*)&As[buf][k][ty * 8 + 4];
            float4 b0 = *(const float4*)&Bs[buf][k][tx * 8];
            float4 b1 = *(const float4*)&Bs[buf][k][tx * 8 + 4];
            unsigned long long bb[4];
            bb[0] = pack2(b0.x, b0.y); bb[1] = pack2(b0.z, b0.w);
            bb[2] = pack2(b1.x, b1.y); bb[3] = pack2(b1.z, b1.w);
#pragma unroll
            for (int i = 0; i < 8; ++i) {
                unsigned long long ai = pack2(a[i], a[i]);
#pragma unroll
                for (int j = 0; j < 4; ++j) fma2(acc2[i][j], ai, bb[j]);
            }
        }
        if (pf) {
            As[buf ^ 1][ah + 0][ar] = av0.x; As[buf ^ 1][ah + 1][ar] = av0.y;
            As[buf ^ 1][ah + 2][ar] = av0.z; As[buf ^ 1][ah + 3][ar] = av0.w;
            As[buf ^ 1][ah + 4][ar] = av1.x; As[buf ^ 1][ah + 5][ar] = av1.y;
            As[buf ^ 1][ah + 6][ar] = av1.z; As[buf ^ 1][ah + 7][ar] = av1.w;
            CP_WAIT0;
            __syncthreads();
        }
    }

#pragma unroll
    for (int i = 0; i < 8; ++i) {
        float c[8];
#pragma unroll
        for (int j = 0; j < 4; ++j) unpack2(c[2 * j], c[2 * j + 1], acc2[i][j]);
        int m = m0 + ty * 8 + i;
        float* crow = C + (size_t)m * N + n0 + tx * 8;
        if (BIAS) {
#pragma unroll
            for (int j = 0; j < 8; ++j) crow[j] = c[j] + bias[n0 + tx * 8 + j];
        } else {
#pragma unroll
            for (int j = 0; j < 8; ++j) crow[j] = c[j];
        }
        if (SPLIT) {
            __align__(16) __nv_bfloat16 pa[8];
#pragma unroll
            for (int j = 0; j < 8; ++j) pa[j] = __float2bfloat16(c[j]);
            *(uint4*)(splitOut + (size_t)m * CDIM + n0 + tx * 8) = *(const uint4*)pa;
        }
    }
}

// ---------------- codebook a-plane + norms ----------------------------------
__global__ void split_cb_kernel(const float* __restrict__ cb,
                                __nv_bfloat16* __restrict__ out)
{
    size_t i = (size_t)blockIdx.x * blockDim.x + threadIdx.x;
    if (i >= (size_t)NCB * CBS * CDIM) return;
    out[i] = __float2bfloat16(cb[i]);
}

// norms + per-stage max||c||^2 (atomicMax on positive-float bits: order-free)
__global__ void norm_kernel(const float* __restrict__ cb, float* __restrict__ out,
                            unsigned* __restrict__ maxC2u, int rows)
{
    int w = (blockIdx.x * blockDim.x + threadIdx.x) >> 5;
    int lane = threadIdx.x & 31;
    if (w >= rows) return;
    const float* r = cb + (size_t)w * CDIM;
    float s = 0.f;
#pragma unroll
    for (int q = 0; q < 4; ++q) { float v = r[lane + q * 32]; s += v * v; }
#pragma unroll
    for (int off = 16; off >= 1; off >>= 1) s += __shfl_xor_sync(0xffffffffu, s, off);
    if (lane == 0) {
        out[w] = s;
        atomicMax(&maxC2u[w >> 10], __float_as_uint(s));
    }
}

// ---------------- phase 1: approx distances, single bf16 pass ---------------
// Per CTA: 128 tokens x 1024 codes, A = bf16(ze) resident (35KB);
// B = 64-code bf16(cb) chunks (17KB) double-buffered. d~ = ||c||^2 - 2*(a.a)
// written as fp16. Error <= ~2^-8*||z||*maxC + fp16 quant (covered by margin).
#define PSTR 272                        // smem row stride (256B data + 16 pad)
#define P1_B (128 * PSTR)               // 34816
#define P1_BBUF (64 * PSTR)             // 17408
#define P1_TOT (P1_B + 2 * P1_BBUF)     // 69632 -> 3 CTAs/SM

__global__ __launch_bounds__(256) void distApprox_kernel(
    const __nv_bfloat16* __restrict__ zeA,   // [BT_TOK][128]
    const __nv_bfloat16* __restrict__ cbA,   // stage base [CBS][128]
    const float* __restrict__ cbn,           // stage base [CBS]
    __half* __restrict__ D)                  // [BT_TOK][CBS]
{
    extern __shared__ char smem[];
    const uint32_t sb = (uint32_t)__cvta_generic_to_shared(smem);
    const int tid = threadIdx.x;
    const int lane = tid & 31, wid = tid >> 5;
    const int rowband = wid & 3;
    const int colhalf = wid >> 2;
    const int gid = lane >> 2, tig = lane & 3;
    const int m0 = blockIdx.x * 128;

    // A: 128 rows x 256B
    {
        const __nv_bfloat16* src = zeA + (size_t)m0 * CDIM;
#pragma unroll
        for (int it = 0; it < 8; ++it) {
            int idx = tid + it * 256;
            int row = idx >> 4, piece = idx & 15;
            cp16(sb + row * PSTR + piece * 16, src + (size_t)row * CDIM + piece * 8);
        }
    }
    CP_COMMIT;
    // B chunk 0
    {
#pragma unroll
        for (int it = 0; it < 4; ++it) {
            int idx = tid + it * 256;
            int row = idx >> 4, piece = idx & 15;
            cp16(sb + P1_B + row * PSTR + piece * 16,
                 cbA + (size_t)row * CDIM + piece * 8);
        }
    }
    CP_COMMIT;

    const uint32_t aBase = sb + (rowband * 32 + (lane & 15)) * PSTR + (lane >> 4) * 16;
    const uint32_t bLaneOff = (colhalf * 32 + (lane & 7)) * PSTR +
                              ((lane >> 3) & 1) * 16;

    float c[2][4][4];
#pragma unroll
    for (int rt = 0; rt < 2; ++rt)
#pragma unroll
        for (int ct = 0; ct < 4; ++ct)
#pragma unroll
            for (int v = 0; v < 4; ++v) c[rt][ct][v] = 0.f;

    for (int nc = 0; nc < 16; ++nc) {
        const int buf = nc & 1;
        if (nc + 1 < 16) {
            const __nv_bfloat16* src = cbA + (size_t)(nc + 1) * 64 * CDIM;
            const uint32_t dst = sb + P1_B + (buf ^ 1) * P1_BBUF;
#pragma unroll
            for (int it = 0; it < 4; ++it) {
                int idx = tid + it * 256;
                int row = idx >> 4, piece = idx & 15;
                cp16(dst + row * PSTR + piece * 16,
                     src + (size_t)row * CDIM + piece * 8);
            }
            CP_COMMIT;
            CP_WAIT1;
        } else {
            CP_WAIT0;
        }
        __syncthreads();

        const uint32_t bBase = sb + P1_B + buf * P1_BBUF + bLaneOff;
#pragma unroll
        for (int kc = 0; kc < 2; ++kc) {
#pragma unroll
            for (int ks = 0; ks < 4; ++ks) {
                const uint32_t off = kc * 128 + ks * 32;
                uint32_t a[2][4];
                LDMX4(a[0], aBase + off);
                LDMX4(a[1], aBase + 16 * PSTR + off);
                uint32_t b[4][2];
#pragma unroll
                for (int ct = 0; ct < 4; ++ct)
                    LDMX2(b[ct], bBase + ct * 8 * PSTR + off);
#pragma unroll
                for (int rt = 0; rt < 2; ++rt)
#pragma unroll
                    for (int ct = 0; ct < 4; ++ct)
                        MMA16816(c[rt][ct], a[rt], b[ct]);
            }
        }

        // write fp16 approx distances for this 64-code chunk
        {
            const int colb = nc * 64 + colhalf * 32;
#pragma unroll
            for (int rt = 0; rt < 2; ++rt) {
                const int row = m0 + rowband * 32 + rt * 16 + gid;
                __half2* d0 = (__half2*)(D + (size_t)row * CBS);
                __half2* d1 = (__half2*)(D + (size_t)(row + 8) * CBS);
#pragma unroll
                for (int ct = 0; ct < 4; ++ct) {
                    const int col = colb + ct * 8 + tig * 2;
                    const float cn0 = cbn[col], cn1 = cbn[col + 1];
                    d0[col >> 1] = __floats2half2_rn(cn0 - 2.0f * c[rt][ct][0],
                                                     cn1 - 2.0f * c[rt][ct][1]);
                    d1[col >> 1] = __floats2half2_rn(cn0 - 2.0f * c[rt][ct][2],
                                                     cn1 - 2.0f * c[rt][ct][3]);
                    c[rt][ct][0] = 0.f; c[rt][ct][1] = 0.f;
                    c[rt][ct][2] = 0.f; c[rt][ct][3] = 0.f;
                }
            }
        }
        __syncthreads();
    }
}

// ---------------- phase 2: certified candidate rescore (exact fp32) ---------
// Per warp = 1 token. margin M = 2^-6*||z||*maxC + 2^-9*(maxC^2+2||z||maxC)
// rigorously covers: dropped bf16 cross/residual terms (<=2^-8*||z||*maxC),
// fp32 accum rounding, fp16 storage quantization (<=2^-11*|d~|), x2 safety.
// Rescore uses the SAME fp32 chain as R4/R10: acc=fma(ze_k,cb_k,acc) k asc;
// d = cbn - 2*acc; min over (monotonic(d)<<32 | n). == full fp32 argmin.
__global__ __launch_bounds__(256) void argminExact_kernel(
    const float* __restrict__ Ze, const __half* __restrict__ D,
    const float* __restrict__ cb, const float* __restrict__ cbn,
    const unsigned* __restrict__ maxC2u, int stage,
    unsigned long long* __restrict__ packed)
{
    __shared__ float zrow[8][128];
    const int lane = threadIdx.x & 31, wid = threadIdx.x >> 5;
    const int t = blockIdx.x * 8 + wid;

    const float* zep = Ze + (size_t)t * CDIM;
    float zn2 = 0.f;
#pragma unroll
    for (int q = 0; q < 4; ++q) {
        float v = zep[lane + q * 32];
        zrow[wid][lane + q * 32] = v;
        zn2 += v * v;
    }
#pragma unroll
    for (int off = 16; off >= 1; off >>= 1)
        zn2 += __shfl_xor_sync(0xffffffffu, zn2, off);
    __syncwarp();

    const float maxC2 = __uint_as_float(maxC2u[stage]);
    const float zn = sqrtf(zn2), maxC = sqrtf(maxC2);
    const float margin = ldexpf(zn * maxC, -6) +
                         ldexpf(maxC2 + 2.0f * zn * maxC, -9);

    const __half2* drow = (const __half2*)(D + (size_t)t * CBS);

    float dmin = 3.4e38f;
#pragma unroll
    for (int i = 0; i < 16; ++i) {
        float2 v = __half22float2(drow[i * 32 + lane]);
        dmin = fminf(dmin, fminf(v.x, v.y));
    }
#pragma unroll
    for (int off = 16; off >= 1; off >>= 1)
        dmin = fminf(dmin, __shfl_xor_sync(0xffffffffu, dmin, off));

    const float thr = dmin + margin;
    unsigned long long best = ~0ull;
    for (int i = 0; i < 16; ++i) {
        float2 v = __half22float2(drow[i * 32 + lane]);
        const int nbase = (i * 32 + lane) * 2;
#pragma unroll
        for (int h = 0; h < 2; ++h) {
            float dv = (h == 0) ? v.x : v.y;
            if (dv <= thr) {
                const int n = nbase + h;
                const float* cr = cb + (size_t)n * CDIM;
                float acc = 0.f;
#pragma unroll 16
                for (int k = 0; k < 128; ++k)
                    acc = fmaf(zrow[wid][k], cr[k], acc);
                float dd = cbn[n] - 2.0f * acc;
                unsigned ib = __float_as_uint(dd);
                ib ^= (ib & 0x80000000u) ? 0xffffffffu : 0x80000000u;
                unsigned long long key = ((unsigned long long)ib << 32) | (unsigned)n;
                if (key < best) best = key;
            }
        }
    }
#pragma unroll
    for (int off = 16; off >= 1; off >>= 1) {
        unsigned long long o = __shfl_xor_sync(0xffffffffu, best, off);
        if (o < best) best = o;
    }
    if (lane == 0) packed[t] = best;
}

// ---------------- per-token fused epilogue ----------------------------------
__global__ __launch_bounds__(128) void fused_update_kernel(
    const float* __restrict__ Ze, const float* __restrict__ cb,
    const float* __restrict__ G, const unsigned long long* __restrict__ packed,
    float* __restrict__ out_codes, int stage, float* __restrict__ partial,
    float* __restrict__ R)
{
    __shared__ float red[128];
    const int t = blockIdx.x;
    const int tid = threadIdx.x;
    const unsigned idx = (unsigned)(packed[t] & 0xffffffffu);

    float d = Ze[(size_t)t * CDIM + tid] - cb[(size_t)idx * CDIM + tid];
    red[tid] = d * d;
    __syncthreads();
#pragma unroll
    for (int st = 64; st > 0; st >>= 1) {
        if (tid < st) red[tid] += red[tid + st];
        __syncthreads();
    }
    if (tid == 0) {
        partial[t] = red[0];
        out_codes[(size_t)t * NCB + stage] = (float)idx;
    }

    float4* R4 = (float4*)(R + (size_t)t * ENC);
    const float4* G4 = (const float4*)(G + (size_t)idx * ENC);
    float4 r = R4[tid];
    float4 g = G4[tid];
    r.x -= g.x; r.y -= g.y; r.z -= g.z; r.w -= g.w;
    R4[tid] = r;
}

__global__ void final_loss_kernel(const float* __restrict__ partial, float* __restrict__ out)
{
    __shared__ float s[256];
    float v = 0.f;
    const int per = (NCB * BT_TOK) / 256;   // 1024
    for (int q = 0; q < per; ++q) v += partial[threadIdx.x * per + q];
    s[threadIdx.x] = v;
    __syncthreads();
    for (int st = 128; st > 0; st >>= 1) {
        if (threadIdx.x < st) s[threadIdx.x] += s[threadIdx.x + st];
        __syncthreads();
    }
    if (threadIdx.x == 0)
        out[(size_t)BT_TOK * NCB] = 1.25f * s[0] / (float)((size_t)BT_TOK * CDIM);
}

// ---------------- launch ----------------------------------------------------
extern "C" void kernel_launch(void* const* d_in, const int* in_sizes, int n_in,
                              void* d_out, int out_size)
{
    const float* z    = (const float*)d_in[0];   // (16,2048,768)
    const float* Win  = (const float*)d_in[1];   // (768,512)
    const float* bin  = (const float*)d_in[2];   // (512,)
    const float* cbs  = (const float*)d_in[3];   // (8,1024,128)
    const float* inw  = (const float*)d_in[4];   // (8,512,128)
    const float* outw = (const float*)d_in[5];   // (8,128,512)
    float* out = (float*)d_out;

    float *gR, *gZe, *gCbn, *gLP, *gG;
    __half* gD;
    __nv_bfloat16 *gZeA, *gCbA;
    unsigned long long* gPk;
    unsigned* gMx;
    cudaGetSymbolAddress((void**)&gR,   g_R);
    cudaGetSymbolAddress((void**)&gZe,  g_Ze);
    cudaGetSymbolAddress((void**)&gZeA, g_zeA);
    cudaGetSymbolAddress((void**)&gCbA, g_cbA);
    cudaGetSymbolAddress((void**)&gCbn, g_cbnorm);
    cudaGetSymbolAddress((void**)&gMx,  g_maxC2u);
    cudaGetSymbolAddress((void**)&gLP,  g_lossPartial);
    cudaGetSymbolAddress((void**)&gG,   g_G);
    cudaGetSymbolAddress((void**)&gPk,  g_packed);
    cudaGetSymbolAddress((void**)&gD,   g_D);

    cudaFuncSetAttribute(distApprox_kernel,
                         cudaFuncAttributeMaxDynamicSharedMemorySize, P1_TOT);

    // 1. residual = z @ W_in + b_in
    sgemm4<true, false><<<dim3(BT_TOK / 128, ENC / 128, 1), 256>>>(
        z, Win, gR, bin, nullptr, IN_DIM, ENC, 0, 0, 0);

    // 2. codebook norms (+ per-stage max) + bf16 a-planes
    norm_kernel<<<(NCB * CBS * 32) / 256, 256>>>(cbs, gCbn, gMx, NCB * CBS);
    split_cb_kernel<<<(NCB * CBS * CDIM) / 256, 256>>>(cbs, gCbA);

    // 3. dec tables: G_i = cb_i @ out_w_i (batched over blockIdx.z)
    sgemm4<false, false><<<dim3(CBS / 128, ENC / 128, NCB), 256>>>(
        cbs, outw, gG, nullptr, nullptr, CDIM, ENC,
        (size_t)CBS * CDIM, (size_t)CDIM * ENC, (size_t)CBS * ENC);

    for (int i = 0; i < NCB; ++i) {
        const float* cb_i = cbs + (size_t)i * CBS * CDIM;

        // z_e = R @ in_w[i]  (fp32 + bf16 a-plane)
        sgemm4<false, true><<<dim3(BT_TOK / 128, CDIM / 128, 1), 256>>>(
            gR, inw + (size_t)i * ENC * CDIM, gZe, nullptr, gZeA, ENC, CDIM, 0, 0, 0);

        // phase 1: approx distances (single bf16 pass)
        distApprox_kernel<<<BT_TOK / 128, 256, P1_TOT>>>(
            gZeA, gCbA + (size_t)i * CBS * CDIM, gCbn + (size_t)i * CBS, gD);

        // phase 2: certified exact fp32 argmin over margin candidates
        argminExact_kernel<<<BT_TOK / 8, 256>>>(
            gZe, gD, cb_i, gCbn + (size_t)i * CBS, gMx, i, gPk);

        // codes + loss partials + R -= G[idx]
        fused_update_kernel<<<BT_TOK, 128>>>(
            gZe, cb_i, gG + (size_t)i * CBS * ENC, gPk, out, i,
            gLP + (size_t)i * BT_TOK, gR);
    }

    final_loss_kernel<<<1, 256>>>(gLP, out);
}